// round 16
// baseline (speedup 1.0000x reference)
#include <cuda_runtime.h>
#include <cstdint>
#include <math.h>

#define NODE_DIM_   128
#define NUM_IRREPS_ 224
#define SPH_DIM_    480
#define HIDDEN_     576
#define NUM_BASIS_  20
#define N_NODES_    30000
#define N_EDGES_    480000
#define EPB_        8
#define MAXD_       32
#define SORT_BLKS_  148

// Scratch (device globals)
__device__ float g_hidden[(size_t)N_NODES_ * NODE_DIM_];
__device__ float g_scalar_out[(size_t)N_NODES_ * HIDDEN_];
__device__ int   g_count[N_NODES_];
__device__ int   g_offs[N_NODES_ + 1];
__device__ int   g_cursor[N_NODES_];
__device__ int   g_perm[N_EDGES_];
__device__ int   g_src_sorted[N_EDGES_];
__device__ float g_fc_sorted[N_EDGES_];
__device__ unsigned int g_syncA;

// ---------------------------------------------------------------------------
__device__ __forceinline__ void grid_barrier(unsigned int* ctr, int nblk) {
    __syncthreads();
    if (threadIdx.x == 0) {
        __threadfence();
        unsigned int arrive = atomicAdd(ctr, 1u) + 1u;
        unsigned int target = ((arrive - 1u) / (unsigned)nblk + 1u) * (unsigned)nblk;
        unsigned int v;
        do {
            asm volatile("ld.acquire.gpu.u32 %0, [%1];" : "=r"(v) : "l"(ctr));
        } while (v < target);
    }
    __syncthreads();
}

// ---------------------------------------------------------------------------
// Fused counting sort (+ sorted src/fc arrays)
// ---------------------------------------------------------------------------
__global__ __launch_bounds__(1024) void sort_kernel(
    const int* __restrict__ edge_index, const float* __restrict__ fcut) {
    const int gsz = gridDim.x * blockDim.x;
    const int gtid = blockIdx.x * blockDim.x + threadIdx.x;

    for (int e = gtid; e < N_EDGES_; e += gsz)
        atomicAdd(&g_count[edge_index[e]], 1);
    grid_barrier(&g_syncA, SORT_BLKS_);

    if (blockIdx.x == 0) {
        __shared__ int s[1024];
        const int C = 30;
        const int t = threadIdx.x;
        const int base = t * C;
        int local[C];
        int sum = 0;
        #pragma unroll
        for (int j = 0; j < C; j++) {
            int i = base + j;
            int v = (i < N_NODES_) ? g_count[i] : 0;
            local[j] = sum;
            sum += v;
        }
        s[t] = sum;
        __syncthreads();
        #pragma unroll
        for (int d = 1; d < 1024; d <<= 1) {
            int x = (t >= d) ? s[t - d] : 0;
            __syncthreads();
            s[t] += x;
            __syncthreads();
        }
        int pre = (t > 0) ? s[t - 1] : 0;
        #pragma unroll
        for (int j = 0; j < C; j++) {
            int i = base + j;
            if (i < N_NODES_) {
                int o = pre + local[j];
                g_offs[i] = o;
                g_cursor[i] = o;
                g_count[i] = 0;
            }
        }
        if (t == 1023) g_offs[N_NODES_] = s[1023];
    }
    grid_barrier(&g_syncA, SORT_BLKS_);

    for (int e = gtid; e < N_EDGES_; e += gsz) {
        int d = edge_index[e];
        int p = atomicAdd(&g_cursor[d], 1);
        g_perm[p] = e;
        g_src_sorted[p] = edge_index[N_EDGES_ + e];
        g_fc_sorted[p] = fcut[e];
    }
}

// ---------------------------------------------------------------------------
// SGEMM 64x64, 4x4 contiguous microtile
// ---------------------------------------------------------------------------
template <bool DO_SILU>
__global__ __launch_bounds__(256) void sgemm_bias(
    const float* __restrict__ A, const float* __restrict__ B,
    const float* __restrict__ bias, float* __restrict__ C,
    int M, int N, int K) {
    __shared__ __align__(16) float As[16][68];
    __shared__ __align__(16) float Bs[16][64];
    const int bm = blockIdx.y * 64;
    const int bn = blockIdx.x * 64;
    const int tid = threadIdx.x;
    const int tx = tid & 15;
    const int ty = tid >> 4;

    float acc[4][4] = {};

    for (int k0 = 0; k0 < K; k0 += 16) {
        #pragma unroll
        for (int i = 0; i < 4; i++) {
            int idx = tid + 256 * i;
            int m = idx >> 4, k = idx & 15;
            int gm = bm + m;
            As[k][m] = (gm < M) ? A[(size_t)gm * K + k0 + k] : 0.0f;
        }
        #pragma unroll
        for (int i = 0; i < 4; i++) {
            int idx = tid + 256 * i;
            int k = idx >> 6, n = idx & 63;
            Bs[k][n] = B[(size_t)(k0 + k) * N + bn + n];
        }
        __syncthreads();
        #pragma unroll
        for (int k = 0; k < 16; k++) {
            float4 aq = *reinterpret_cast<const float4*>(&As[k][ty * 4]);
            float4 bq = *reinterpret_cast<const float4*>(&Bs[k][tx * 4]);
            float a[4] = {aq.x, aq.y, aq.z, aq.w};
            float b[4] = {bq.x, bq.y, bq.z, bq.w};
            #pragma unroll
            for (int i = 0; i < 4; i++)
                #pragma unroll
                for (int j = 0; j < 4; j++)
                    acc[i][j] = fmaf(a[i], b[j], acc[i][j]);
        }
        __syncthreads();
    }

    float4 bq = *reinterpret_cast<const float4*>(&bias[bn + tx * 4]);
    float bv[4] = {bq.x, bq.y, bq.z, bq.w};
    #pragma unroll
    for (int i = 0; i < 4; i++) {
        int m = bm + ty * 4 + i;
        if (m >= M) continue;
        float4 o;
        float* op = &o.x;
        #pragma unroll
        for (int j = 0; j < 4; j++) {
            float v = acc[i][j] + bv[j];
            if (DO_SILU) v = v / (1.0f + expf(-v));
            op[j] = v;
        }
        *reinterpret_cast<float4*>(&C[(size_t)m * N + bn + tx * 4]) = o;
    }
}

// ---------------------------------------------------------------------------
// Scalar kernel S: 2 nodes per 256-thread block, unroll-2 edge loop.
// ---------------------------------------------------------------------------
__global__ __launch_bounds__(256) void scalar_kernel(
    const float* __restrict__ rbf,
    const float* __restrict__ Wrbf, const float* __restrict__ brbf,
    const float* __restrict__ x_scalar, float* __restrict__ out_scalar) {
    const float* __restrict__ so = g_scalar_out;

    const int t = threadIdx.x & 127;
    const int n = blockIdx.x * 2 + (threadIdx.x >> 7);
    if (n >= N_NODES_) return;
    const int col = 2 * NUM_IRREPS_ + t;      // 448 + t

    float w[NUM_BASIS_];
    #pragma unroll
    for (int k = 0; k < NUM_BASIS_; k++) w[k] = __ldg(&Wrbf[k * HIDDEN_ + col]);
    const float bb = __ldg(&brbf[col]);

    const int off = g_offs[n];
    const int deg = g_offs[n + 1] - off;

    float acc = 0.0f;
    #pragma unroll 2
    for (int g = 0; g < deg; g++) {
        int eid = __ldg(&g_perm[off + g]);
        int src = __ldg(&g_src_sorted[off + g]);
        float fc = __ldg(&g_fc_sorted[off + g]);

        const float4* rq = reinterpret_cast<const float4*>(
            rbf + (size_t)eid * NUM_BASIS_);
        float4 q0 = __ldg(rq), q1 = __ldg(rq + 1), q2 = __ldg(rq + 2),
               q3 = __ldg(rq + 3), q4 = __ldg(rq + 4);

        float sv = __ldg(&so[(size_t)src * HIDDEN_ + col]);

        float v = bb;
        v = fmaf(q0.x, w[0],  v); v = fmaf(q0.y, w[1],  v);
        v = fmaf(q0.z, w[2],  v); v = fmaf(q0.w, w[3],  v);
        v = fmaf(q1.x, w[4],  v); v = fmaf(q1.y, w[5],  v);
        v = fmaf(q1.z, w[6],  v); v = fmaf(q1.w, w[7],  v);
        v = fmaf(q2.x, w[8],  v); v = fmaf(q2.y, w[9],  v);
        v = fmaf(q2.z, w[10], v); v = fmaf(q2.w, w[11], v);
        v = fmaf(q3.x, w[12], v); v = fmaf(q3.y, w[13], v);
        v = fmaf(q3.z, w[14], v); v = fmaf(q3.w, w[15], v);
        v = fmaf(q4.x, w[16], v); v = fmaf(q4.y, w[17], v);
        v = fmaf(q4.z, w[18], v); v = fmaf(q4.w, w[19], v);

        acc = fmaf(sv, v * fc, acc);
    }

    out_scalar[(size_t)n * NODE_DIM_ + t] =
        x_scalar[(size_t)n * NODE_DIM_ + t] + acc;
}

// ---------------------------------------------------------------------------
// Spherical kernel P: 480 threads, 2 blocks/SM (30 warps).
// rsh (DRAM stream) pipelined one batch ahead in registers.
// ---------------------------------------------------------------------------
__device__ __forceinline__ int irrep_of(int k) {
    if (k < 128) return k;
    if (k < 320) return 128 + (k - 128) / 3;
    return 192 + (k - 320) / 5;
}

__global__ __launch_bounds__(480, 2) void sph_kernel(
    const float* __restrict__ rbf, const float* __restrict__ rsh,
    const float* __restrict__ Wrbf, const float* __restrict__ brbf,
    const float* __restrict__ x_sph, float* __restrict__ out_sph) {
    const float* __restrict__ so = g_scalar_out;

    __shared__ __align__(16) float rbf_s[MAXD_][24];
    __shared__ int   eid_s[MAXD_];
    __shared__ int   src_s[MAXD_];
    __shared__ float fc_s[MAXD_];
    __shared__ float gate_s[2][EPB_][2 * NUM_IRREPS_];

    const int t = threadIdx.x;
    const bool gcol = (t < 2 * NUM_IRREPS_);
    const int wcol = gcol ? t : 0;

    float w[NUM_BASIS_];
    #pragma unroll
    for (int k = 0; k < NUM_BASIS_; k++) w[k] = Wrbf[k * HIDDEN_ + wcol];
    const float bb = brbf[wcol];
    const int ir = irrep_of(t);

    for (int n = blockIdx.x; n < N_NODES_; n += gridDim.x) {
        const int off = g_offs[n];
        const int deg = g_offs[n + 1] - off;

        float acc = 0.0f;

        for (int c0 = 0; c0 < deg; c0 += MAXD_) {
            const int cnt = min(MAXD_, deg - c0);
            const int bp = off + c0;

            __syncthreads();   // prev chunk smem consumed

            if (t < MAXD_) {
                int jj = (t < cnt) ? t : cnt - 1;
                eid_s[t] = __ldg(&g_perm[bp + jj]);
                src_s[t] = __ldg(&g_src_sorted[bp + jj]);
                fc_s[t]  = (t < cnt) ? __ldg(&g_fc_sorted[bp + t]) : 0.0f;
            }
            for (int i = t; i < cnt * NUM_BASIS_; i += 480) {
                int e = i / NUM_BASIS_, k = i - e * NUM_BASIS_;
                int eid = __ldg(&g_perm[bp + e]);     // L1 broadcast
                rbf_s[e][k] = __ldg(&rbf[(size_t)eid * NUM_BASIS_ + k]);
            }
            __syncthreads();

            const int nb = (cnt + EPB_ - 1) / EPB_;

            // rsh pipeline: rvA = batch 0's rsh, issued right after meta barrier
            float rvA[EPB_], rvN[EPB_];
            #pragma unroll
            for (int e = 0; e < EPB_; e++)
                rvA[e] = __ldcs(&rsh[(size_t)eid_s[e] * SPH_DIM_ + t]);

            for (int b = 0; b < nb; b++) {
                const int base = b * EPB_;

                // this batch's so/x gathers + next batch's rsh
                float s[EPB_], xv[EPB_];
                #pragma unroll
                for (int e = 0; e < EPB_; e++) {
                    int sp = src_s[base + e];
                    s[e]  = gcol ? __ldg(&so[(size_t)sp * HIDDEN_ + t]) : 0.0f;
                    xv[e] = __ldg(&x_sph[(size_t)sp * SPH_DIM_ + t]);
                }
                if (b + 1 < nb) {
                    #pragma unroll
                    for (int e = 0; e < EPB_; e++)
                        rvN[e] = __ldcs(
                            &rsh[(size_t)eid_s[base + EPB_ + e] * SPH_DIM_ + t]);
                }

                if (gcol) {
                    float a[EPB_];
                    #pragma unroll
                    for (int e = 0; e < EPB_; e++) {
                        const float4* rp =
                            reinterpret_cast<const float4*>(&rbf_s[base + e][0]);
                        float4 q0 = rp[0], q1 = rp[1], q2 = rp[2], q3 = rp[3],
                               q4 = rp[4];
                        float v = bb;
                        v = fmaf(q0.x, w[0],  v); v = fmaf(q0.y, w[1],  v);
                        v = fmaf(q0.z, w[2],  v); v = fmaf(q0.w, w[3],  v);
                        v = fmaf(q1.x, w[4],  v); v = fmaf(q1.y, w[5],  v);
                        v = fmaf(q1.z, w[6],  v); v = fmaf(q1.w, w[7],  v);
                        v = fmaf(q2.x, w[8],  v); v = fmaf(q2.y, w[9],  v);
                        v = fmaf(q2.z, w[10], v); v = fmaf(q2.w, w[11], v);
                        v = fmaf(q3.x, w[12], v); v = fmaf(q3.y, w[13], v);
                        v = fmaf(q3.z, w[14], v); v = fmaf(q3.w, w[15], v);
                        v = fmaf(q4.x, w[16], v); v = fmaf(q4.y, w[17], v);
                        v = fmaf(q4.z, w[18], v); v = fmaf(q4.w, w[19], v);
                        a[e] = v;
                    }
                    #pragma unroll
                    for (int e = 0; e < EPB_; e++)
                        gate_s[b & 1][e][t] = s[e] * (a[e] * fc_s[base + e]);
                }
                __syncthreads();   // gates ready

                #pragma unroll
                for (int e = 0; e < EPB_; e++) {
                    const float* ge = gate_s[b & 1][e];
                    acc = fmaf(xv[e], ge[ir], acc);
                    acc = fmaf(rvA[e], ge[NUM_IRREPS_ + ir], acc);
                }
                #pragma unroll
                for (int e = 0; e < EPB_; e++) rvA[e] = rvN[e];
            }
        }

        out_sph[(size_t)n * SPH_DIM_ + t] =
            x_sph[(size_t)n * SPH_DIM_ + t] + acc;
    }
}

// ---------------------------------------------------------------------------
extern "C" void kernel_launch(void* const* d_in, const int* in_sizes, int n_in,
                              void* d_out, int out_size) {
    const float* x_scalar = (const float*)d_in[0];
    const float* x_sph    = (const float*)d_in[1];
    const float* rbf      = (const float*)d_in[2];
    const float* fcut     = (const float*)d_in[3];
    const float* rsh      = (const float*)d_in[4];
    const int*   eidx     = (const int*)d_in[5];
    const float* W1       = (const float*)d_in[6];
    const float* b1       = (const float*)d_in[7];
    const float* W2       = (const float*)d_in[8];
    const float* b2       = (const float*)d_in[9];
    const float* Wrbf     = (const float*)d_in[10];
    const float* brbf     = (const float*)d_in[11];

    float* out        = (float*)d_out;
    float* out_scalar = out;
    float* out_sph    = out + (size_t)N_NODES_ * NODE_DIM_;

    float* hidden = nullptr;
    float* so     = nullptr;
    cudaGetSymbolAddress((void**)&hidden, g_hidden);
    cudaGetSymbolAddress((void**)&so, g_scalar_out);

    sort_kernel<<<SORT_BLKS_, 1024>>>(eidx, fcut);                           // 0
    {
        dim3 grid(NODE_DIM_ / 64, (N_NODES_ + 63) / 64);
        sgemm_bias<true><<<grid, 256>>>(x_scalar, W1, b1, hidden,
                                        N_NODES_, NODE_DIM_, NODE_DIM_);     // 1
    }
    {
        dim3 grid(HIDDEN_ / 64, (N_NODES_ + 63) / 64);
        sgemm_bias<false><<<grid, 256>>>(hidden, W2, b2, so,
                                         N_NODES_, HIDDEN_, NODE_DIM_);      // 2
    }
    scalar_kernel<<<(N_NODES_ + 1) / 2, 256>>>(rbf, Wrbf, brbf,
                                               x_scalar, out_scalar);        // 3
    sph_kernel<<<296, 480>>>(rbf, rsh, Wrbf, brbf, x_sph, out_sph);          // 4
}

// round 17
// speedup vs baseline: 1.3755x; 1.3755x over previous
#include <cuda_runtime.h>
#include <cstdint>
#include <math.h>

#define NODE_DIM_   128
#define NUM_IRREPS_ 224
#define SPH_DIM_    480
#define HIDDEN_     576
#define NUM_BASIS_  20
#define N_NODES_    30000
#define N_EDGES_    480000
#define EPB_        8
#define MAXD_       32
#define SORT_BLKS_  148

// Scratch (device globals)
__device__ float g_hidden[(size_t)N_NODES_ * NODE_DIM_];
__device__ float g_scalar_out[(size_t)N_NODES_ * HIDDEN_];
__device__ int   g_count[N_NODES_];
__device__ int   g_offs[N_NODES_ + 1];
__device__ int   g_cursor[N_NODES_];
__device__ int   g_perm[N_EDGES_];
__device__ int   g_src_sorted[N_EDGES_];
__device__ float g_fc_sorted[N_EDGES_];
__device__ unsigned int g_syncA;

// ---------------------------------------------------------------------------
__device__ __forceinline__ void grid_barrier(unsigned int* ctr, int nblk) {
    __syncthreads();
    if (threadIdx.x == 0) {
        __threadfence();
        unsigned int arrive = atomicAdd(ctr, 1u) + 1u;
        unsigned int target = ((arrive - 1u) / (unsigned)nblk + 1u) * (unsigned)nblk;
        unsigned int v;
        do {
            asm volatile("ld.acquire.gpu.u32 %0, [%1];" : "=r"(v) : "l"(ctr));
        } while (v < target);
    }
    __syncthreads();
}

// ---------------------------------------------------------------------------
// Fused counting sort (+ sorted src/fc arrays)
// ---------------------------------------------------------------------------
__global__ __launch_bounds__(1024) void sort_kernel(
    const int* __restrict__ edge_index, const float* __restrict__ fcut) {
    const int gsz = gridDim.x * blockDim.x;
    const int gtid = blockIdx.x * blockDim.x + threadIdx.x;

    for (int e = gtid; e < N_EDGES_; e += gsz)
        atomicAdd(&g_count[edge_index[e]], 1);
    grid_barrier(&g_syncA, SORT_BLKS_);

    if (blockIdx.x == 0) {
        __shared__ int s[1024];
        const int C = 30;
        const int t = threadIdx.x;
        const int base = t * C;
        int local[C];
        int sum = 0;
        #pragma unroll
        for (int j = 0; j < C; j++) {
            int i = base + j;
            int v = (i < N_NODES_) ? g_count[i] : 0;
            local[j] = sum;
            sum += v;
        }
        s[t] = sum;
        __syncthreads();
        #pragma unroll
        for (int d = 1; d < 1024; d <<= 1) {
            int x = (t >= d) ? s[t - d] : 0;
            __syncthreads();
            s[t] += x;
            __syncthreads();
        }
        int pre = (t > 0) ? s[t - 1] : 0;
        #pragma unroll
        for (int j = 0; j < C; j++) {
            int i = base + j;
            if (i < N_NODES_) {
                int o = pre + local[j];
                g_offs[i] = o;
                g_cursor[i] = o;
                g_count[i] = 0;
            }
        }
        if (t == 1023) g_offs[N_NODES_] = s[1023];
    }
    grid_barrier(&g_syncA, SORT_BLKS_);

    for (int e = gtid; e < N_EDGES_; e += gsz) {
        int d = edge_index[e];
        int p = atomicAdd(&g_cursor[d], 1);
        g_perm[p] = e;
        g_src_sorted[p] = edge_index[N_EDGES_ + e];
        g_fc_sorted[p] = fcut[e];
    }
}

// ---------------------------------------------------------------------------
// SGEMM 64x64, 4x4 contiguous microtile
// ---------------------------------------------------------------------------
template <bool DO_SILU>
__global__ __launch_bounds__(256) void sgemm_bias(
    const float* __restrict__ A, const float* __restrict__ B,
    const float* __restrict__ bias, float* __restrict__ C,
    int M, int N, int K) {
    __shared__ __align__(16) float As[16][68];
    __shared__ __align__(16) float Bs[16][64];
    const int bm = blockIdx.y * 64;
    const int bn = blockIdx.x * 64;
    const int tid = threadIdx.x;
    const int tx = tid & 15;
    const int ty = tid >> 4;

    float acc[4][4] = {};

    for (int k0 = 0; k0 < K; k0 += 16) {
        #pragma unroll
        for (int i = 0; i < 4; i++) {
            int idx = tid + 256 * i;
            int m = idx >> 4, k = idx & 15;
            int gm = bm + m;
            As[k][m] = (gm < M) ? A[(size_t)gm * K + k0 + k] : 0.0f;
        }
        #pragma unroll
        for (int i = 0; i < 4; i++) {
            int idx = tid + 256 * i;
            int k = idx >> 6, n = idx & 63;
            Bs[k][n] = B[(size_t)(k0 + k) * N + bn + n];
        }
        __syncthreads();
        #pragma unroll
        for (int k = 0; k < 16; k++) {
            float4 aq = *reinterpret_cast<const float4*>(&As[k][ty * 4]);
            float4 bq = *reinterpret_cast<const float4*>(&Bs[k][tx * 4]);
            float a[4] = {aq.x, aq.y, aq.z, aq.w};
            float b[4] = {bq.x, bq.y, bq.z, bq.w};
            #pragma unroll
            for (int i = 0; i < 4; i++)
                #pragma unroll
                for (int j = 0; j < 4; j++)
                    acc[i][j] = fmaf(a[i], b[j], acc[i][j]);
        }
        __syncthreads();
    }

    float4 bq = *reinterpret_cast<const float4*>(&bias[bn + tx * 4]);
    float bv[4] = {bq.x, bq.y, bq.z, bq.w};
    #pragma unroll
    for (int i = 0; i < 4; i++) {
        int m = bm + ty * 4 + i;
        if (m >= M) continue;
        float4 o;
        float* op = &o.x;
        #pragma unroll
        for (int j = 0; j < 4; j++) {
            float v = acc[i][j] + bv[j];
            if (DO_SILU) v = v / (1.0f + expf(-v));
            op[j] = v;
        }
        *reinterpret_cast<float4*>(&C[(size_t)m * N + bn + tx * 4]) = o;
    }
}

// ---------------------------------------------------------------------------
// Scalar kernel: 1 node per 128-thread block, sph-style batched structure:
// smem-staged rbf/meta per 16-edge chunk, 8-deep independent so gathers.
// ---------------------------------------------------------------------------
#define SMAXD_ 16
__global__ __launch_bounds__(128) void scalar_kernel(
    const float* __restrict__ rbf,
    const float* __restrict__ Wrbf, const float* __restrict__ brbf,
    const float* __restrict__ x_scalar, float* __restrict__ out_scalar) {
    const float* __restrict__ so = g_scalar_out;

    __shared__ __align__(16) float rbf_s[SMAXD_][24];
    __shared__ int   src_s[SMAXD_];
    __shared__ float fc_s[SMAXD_];

    const int t = threadIdx.x;
    const int n = blockIdx.x;
    const int col = 2 * NUM_IRREPS_ + t;      // 448 + t

    float w[NUM_BASIS_];
    #pragma unroll
    for (int k = 0; k < NUM_BASIS_; k++) w[k] = __ldg(&Wrbf[k * HIDDEN_ + col]);
    const float bb = __ldg(&brbf[col]);

    const int off = g_offs[n];
    const int deg = g_offs[n + 1] - off;

    float acc = 0.0f;
    for (int c0 = 0; c0 < deg; c0 += SMAXD_) {
        const int cnt = min(SMAXD_, deg - c0);
        const int bp = off + c0;

        __syncthreads();
        if (t < SMAXD_) {
            int jj = (t < cnt) ? t : cnt - 1;
            src_s[t] = __ldg(&g_src_sorted[bp + jj]);
            fc_s[t]  = (t < cnt) ? __ldg(&g_fc_sorted[bp + t]) : 0.0f;
        }
        for (int i = t; i < cnt * NUM_BASIS_; i += 128) {
            int e = i / NUM_BASIS_, k = i - e * NUM_BASIS_;
            int eid = __ldg(&g_perm[bp + e]);       // L1 broadcast
            rbf_s[e][k] = __ldg(&rbf[(size_t)eid * NUM_BASIS_ + k]);
        }
        __syncthreads();

        const int nb = (cnt + EPB_ - 1) / EPB_;     // 1..2
        for (int b = 0; b < nb; b++) {
            const int base = b * EPB_;

            float sv[EPB_];
            #pragma unroll
            for (int e = 0; e < EPB_; e++)
                sv[e] = __ldg(&so[(size_t)src_s[base + e] * HIDDEN_ + col]);

            #pragma unroll
            for (int e = 0; e < EPB_; e++) {
                const float4* rp =
                    reinterpret_cast<const float4*>(&rbf_s[base + e][0]);
                float4 q0 = rp[0], q1 = rp[1], q2 = rp[2], q3 = rp[3], q4 = rp[4];
                float v = bb;
                v = fmaf(q0.x, w[0],  v); v = fmaf(q0.y, w[1],  v);
                v = fmaf(q0.z, w[2],  v); v = fmaf(q0.w, w[3],  v);
                v = fmaf(q1.x, w[4],  v); v = fmaf(q1.y, w[5],  v);
                v = fmaf(q1.z, w[6],  v); v = fmaf(q1.w, w[7],  v);
                v = fmaf(q2.x, w[8],  v); v = fmaf(q2.y, w[9],  v);
                v = fmaf(q2.z, w[10], v); v = fmaf(q2.w, w[11], v);
                v = fmaf(q3.x, w[12], v); v = fmaf(q3.y, w[13], v);
                v = fmaf(q3.z, w[14], v); v = fmaf(q3.w, w[15], v);
                v = fmaf(q4.x, w[16], v); v = fmaf(q4.y, w[17], v);
                v = fmaf(q4.z, w[18], v); v = fmaf(q4.w, w[19], v);
                acc = fmaf(sv[e], v * fc_s[base + e], acc);
            }
        }
    }

    out_scalar[(size_t)n * NODE_DIM_ + t] =
        x_scalar[(size_t)n * NODE_DIM_ + t] + acc;
}

// ---------------------------------------------------------------------------
// Spherical kernel P: EXACT R15 version (measured 845us; 64 regs, 2 blk/SM).
// ---------------------------------------------------------------------------
__device__ __forceinline__ int irrep_of(int k) {
    if (k < 128) return k;
    if (k < 320) return 128 + (k - 128) / 3;
    return 192 + (k - 320) / 5;
}

__global__ __launch_bounds__(480, 2) void sph_kernel(
    const float* __restrict__ rbf, const float* __restrict__ rsh,
    const float* __restrict__ Wrbf, const float* __restrict__ brbf,
    const float* __restrict__ x_sph, float* __restrict__ out_sph) {
    const float* __restrict__ so = g_scalar_out;

    __shared__ __align__(16) float rbf_s[MAXD_][24];
    __shared__ int   eid_s[MAXD_];
    __shared__ int   src_s[MAXD_];
    __shared__ float fc_s[MAXD_];
    __shared__ float gate_s[2][EPB_][2 * NUM_IRREPS_];

    const int t = threadIdx.x;
    const bool gcol = (t < 2 * NUM_IRREPS_);
    const int wcol = gcol ? t : 0;

    float w[NUM_BASIS_];
    #pragma unroll
    for (int k = 0; k < NUM_BASIS_; k++) w[k] = Wrbf[k * HIDDEN_ + wcol];
    const float bb = brbf[wcol];
    const int ir = irrep_of(t);

    for (int n = blockIdx.x; n < N_NODES_; n += gridDim.x) {
        const int off = g_offs[n];
        const int deg = g_offs[n + 1] - off;

        float acc = 0.0f;

        for (int c0 = 0; c0 < deg; c0 += MAXD_) {
            const int cnt = min(MAXD_, deg - c0);
            const int bp = off + c0;

            __syncthreads();   // prev chunk smem consumed

            if (t < MAXD_) {
                int jj = (t < cnt) ? t : cnt - 1;
                eid_s[t] = __ldg(&g_perm[bp + jj]);
                src_s[t] = __ldg(&g_src_sorted[bp + jj]);
                fc_s[t]  = (t < cnt) ? __ldg(&g_fc_sorted[bp + t]) : 0.0f;
            }
            for (int i = t; i < cnt * NUM_BASIS_; i += 480) {
                int e = i / NUM_BASIS_, k = i - e * NUM_BASIS_;
                int eid = __ldg(&g_perm[bp + e]);     // L1 broadcast
                rbf_s[e][k] = __ldg(&rbf[(size_t)eid * NUM_BASIS_ + k]);
            }
            __syncthreads();

            const int nb = (cnt + EPB_ - 1) / EPB_;
            for (int b = 0; b < nb; b++) {
                const int base = b * EPB_;

                float s[EPB_], xv[EPB_], rv[EPB_];
                #pragma unroll
                for (int e = 0; e < EPB_; e++) {
                    int sp = src_s[base + e];
                    s[e]  = gcol ? __ldg(&so[(size_t)sp * HIDDEN_ + t]) : 0.0f;
                    xv[e] = __ldg(&x_sph[(size_t)sp * SPH_DIM_ + t]);
                    rv[e] = __ldcs(&rsh[(size_t)eid_s[base + e] * SPH_DIM_ + t]);
                }

                if (gcol) {
                    float a[EPB_];
                    #pragma unroll
                    for (int e = 0; e < EPB_; e++) {
                        const float4* rp =
                            reinterpret_cast<const float4*>(&rbf_s[base + e][0]);
                        float4 q0 = rp[0], q1 = rp[1], q2 = rp[2], q3 = rp[3],
                               q4 = rp[4];
                        float v = bb;
                        v = fmaf(q0.x, w[0],  v); v = fmaf(q0.y, w[1],  v);
                        v = fmaf(q0.z, w[2],  v); v = fmaf(q0.w, w[3],  v);
                        v = fmaf(q1.x, w[4],  v); v = fmaf(q1.y, w[5],  v);
                        v = fmaf(q1.z, w[6],  v); v = fmaf(q1.w, w[7],  v);
                        v = fmaf(q2.x, w[8],  v); v = fmaf(q2.y, w[9],  v);
                        v = fmaf(q2.z, w[10], v); v = fmaf(q2.w, w[11], v);
                        v = fmaf(q3.x, w[12], v); v = fmaf(q3.y, w[13], v);
                        v = fmaf(q3.z, w[14], v); v = fmaf(q3.w, w[15], v);
                        v = fmaf(q4.x, w[16], v); v = fmaf(q4.y, w[17], v);
                        v = fmaf(q4.z, w[18], v); v = fmaf(q4.w, w[19], v);
                        a[e] = v;
                    }
                    #pragma unroll
                    for (int e = 0; e < EPB_; e++)
                        gate_s[b & 1][e][t] = s[e] * (a[e] * fc_s[base + e]);
                }
                __syncthreads();   // gates ready; gathers land during wait

                #pragma unroll
                for (int e = 0; e < EPB_; e++) {
                    const float* ge = gate_s[b & 1][e];
                    acc = fmaf(xv[e], ge[ir], acc);
                    acc = fmaf(rv[e], ge[NUM_IRREPS_ + ir], acc);
                }
            }
        }

        out_sph[(size_t)n * SPH_DIM_ + t] =
            x_sph[(size_t)n * SPH_DIM_ + t] + acc;
    }
}

// ---------------------------------------------------------------------------
extern "C" void kernel_launch(void* const* d_in, const int* in_sizes, int n_in,
                              void* d_out, int out_size) {
    const float* x_scalar = (const float*)d_in[0];
    const float* x_sph    = (const float*)d_in[1];
    const float* rbf      = (const float*)d_in[2];
    const float* fcut     = (const float*)d_in[3];
    const float* rsh      = (const float*)d_in[4];
    const int*   eidx     = (const int*)d_in[5];
    const float* W1       = (const float*)d_in[6];
    const float* b1       = (const float*)d_in[7];
    const float* W2       = (const float*)d_in[8];
    const float* b2       = (const float*)d_in[9];
    const float* Wrbf     = (const float*)d_in[10];
    const float* brbf     = (const float*)d_in[11];

    float* out        = (float*)d_out;
    float* out_scalar = out;
    float* out_sph    = out + (size_t)N_NODES_ * NODE_DIM_;

    float* hidden = nullptr;
    float* so     = nullptr;
    cudaGetSymbolAddress((void**)&hidden, g_hidden);
    cudaGetSymbolAddress((void**)&so, g_scalar_out);

    sort_kernel<<<SORT_BLKS_, 1024>>>(eidx, fcut);                           // 0
    {
        dim3 grid(NODE_DIM_ / 64, (N_NODES_ + 63) / 64);
        sgemm_bias<true><<<grid, 256>>>(x_scalar, W1, b1, hidden,
                                        N_NODES_, NODE_DIM_, NODE_DIM_);     // 1
    }
    {
        dim3 grid(HIDDEN_ / 64, (N_NODES_ + 63) / 64);
        sgemm_bias<false><<<grid, 256>>>(hidden, W2, b2, so,
                                         N_NODES_, HIDDEN_, NODE_DIM_);      // 2
    }
    scalar_kernel<<<N_NODES_, 128>>>(rbf, Wrbf, brbf, x_scalar, out_scalar); // 3
    sph_kernel<<<296, 480>>>(rbf, rsh, Wrbf, brbf, x_sph, out_sph);          // 4
}